// round 2
// baseline (speedup 1.0000x reference)
#include <cuda_runtime.h>
#include <math.h>

#define B_ 8
#define T_ 2048
#define C_ 512
#define H_ 64

// Intermediate Q,K,V (no device allocation allowed -> __device__ globals)
__device__ float g_q[B_ * T_ * H_];
__device__ float g_k[B_ * T_ * H_];
__device__ float g_v[B_ * T_ * H_];

// ---------------------------------------------------------------------------
// Kernel 1: fused QKV projection.  [16384 x 512] @ [512 x 192] (Wq|Wk|Wv)
// Block: 256 threads as 16x16; tile M=64, N=192, K-chunk=32.
// Each thread: 4 rows x 12 cols register tile.
// ---------------------------------------------------------------------------
__global__ __launch_bounds__(256) void qkv_proj_kernel(
    const float* __restrict__ x,
    const float* __restrict__ Wq,
    const float* __restrict__ Wk,
    const float* __restrict__ Wv) {
    __shared__ float xT[32][68];    // transposed x chunk: [k][row], padded
    __shared__ float ws[32][196];   // W chunk: [k][n], padded (196*4 = 16B-aligned rows)

    const int tid = threadIdx.x;
    const int tx = tid & 15;        // col group (0..15) -> cols tx*12 .. tx*12+11
    const int ty = tid >> 4;        // row group (0..15) -> rows ty*4  .. ty*4+3
    const int row0 = blockIdx.x * 64;

    float acc[4][12];
#pragma unroll
    for (int i = 0; i < 4; i++)
#pragma unroll
        for (int j = 0; j < 12; j++) acc[i][j] = 0.f;

    for (int k0 = 0; k0 < C_; k0 += 32) {
        // load x tile transposed (coalesced 32-float row segments)
        for (int idx = tid; idx < 64 * 32; idx += 256) {
            int r = idx >> 5, k = idx & 31;
            xT[k][r] = x[(size_t)(row0 + r) * C_ + k0 + k];
        }
        // load W chunk [32 x 192] from the three matrices
        for (int idx = tid; idx < 32 * 192; idx += 256) {
            int k = idx / 192, n = idx % 192;
            int kk = k0 + k;
            float w;
            if (n < 64)       w = Wq[kk * H_ + n];
            else if (n < 128) w = Wk[kk * H_ + (n - 64)];
            else              w = Wv[kk * H_ + (n - 128)];
            ws[k][n] = w;
        }
        __syncthreads();

#pragma unroll
        for (int k = 0; k < 32; k++) {
            float4 xv = *(const float4*)&xT[k][ty * 4];
            float xr[4] = {xv.x, xv.y, xv.z, xv.w};
            float wr[12];
            *(float4*)&wr[0] = *(const float4*)&ws[k][tx * 12];
            *(float4*)&wr[4] = *(const float4*)&ws[k][tx * 12 + 4];
            *(float4*)&wr[8] = *(const float4*)&ws[k][tx * 12 + 8];
#pragma unroll
            for (int i = 0; i < 4; i++)
#pragma unroll
                for (int j = 0; j < 12; j++)
                    acc[i][j] = fmaf(xr[i], wr[j], acc[i][j]);
        }
        __syncthreads();
    }

#pragma unroll
    for (int i = 0; i < 4; i++) {
        size_t row = (size_t)row0 + ty * 4 + i;
#pragma unroll
        for (int j = 0; j < 12; j++) {
            int n = tx * 12 + j;
            float v = acc[i][j];
            if (n < 64)       g_q[row * H_ + n] = v;
            else if (n < 128) g_k[row * H_ + (n - 64)] = v;
            else              g_v[row * H_ + (n - 128)] = v;
        }
    }
}

// ---------------------------------------------------------------------------
// Kernel 2: flash attention.  One block per (batch, 64-query tile).
// 256 threads as 16x16.  Online softmax over 32 key tiles of 64.
// smem (dynamic, 67 KB): qT[64][68], kT[64][68], ps[64][68], vs[64][64]
// ---------------------------------------------------------------------------
#define QT_OFF  0
#define KT_OFF  4352          // 64*68
#define PS_OFF  8704
#define VS_OFF  13056
#define ATT_SMEM ((13056 + 4096) * 4)   // 68608 bytes

__global__ __launch_bounds__(256) void attn_kernel(float* __restrict__ out) {
    extern __shared__ float sm[];
    float* qT = sm + QT_OFF;
    float* kT = sm + KT_OFF;
    float* ps = sm + PS_OFF;
    float* vs = sm + VS_OFF;

    const int tid = threadIdx.x;
    const int tx = tid & 15;    // key/head-col group
    const int ty = tid >> 4;    // query-row group
    const int b  = blockIdx.y;
    const int q0 = blockIdx.x * 64;
    const float scale = rsqrtf((float)C_);   // reference uses C**-0.5

    const float* Qg = g_q + ((size_t)b * T_ + q0) * H_;
    const float* Kg = g_k + (size_t)b * T_ * H_;
    const float* Vg = g_v + (size_t)b * T_ * H_;

    // load Q tile transposed, scale folded in
    for (int idx = tid; idx < 64 * 64; idx += 256) {
        int r = idx >> 6, d = idx & 63;
        qT[d * 68 + r] = Qg[r * H_ + d] * scale;
    }

    float m[4], l[4], o[4][4];
#pragma unroll
    for (int i = 0; i < 4; i++) {
        m[i] = -INFINITY;
        l[i] = 0.f;
#pragma unroll
        for (int j = 0; j < 4; j++) o[i][j] = 0.f;
    }

    for (int t0 = 0; t0 < T_; t0 += 64) {
        __syncthreads();   // prior iter done reading ps/vs
        // load K tile transposed
        for (int idx = tid; idx < 64 * 64; idx += 256) {
            int r = idx >> 6, d = idx & 63;
            kT[d * 68 + r] = Kg[(size_t)(t0 + r) * H_ + d];
        }
        // load V tile (row-major, float4 coalesced)
        for (int idx = tid * 4; idx < 64 * 64; idx += 256 * 4) {
            *(float4*)&vs[idx] = *(const float4*)&Vg[(size_t)t0 * H_ + idx];
        }
        __syncthreads();

        // S = Q K^T  (each thread 4x4)
        float s[4][4];
#pragma unroll
        for (int i = 0; i < 4; i++)
#pragma unroll
            for (int j = 0; j < 4; j++) s[i][j] = 0.f;

#pragma unroll
        for (int d = 0; d < 64; d++) {
            float4 qv = *(const float4*)&qT[d * 68 + ty * 4];
            float4 kv = *(const float4*)&kT[d * 68 + tx * 4];
            float qr[4] = {qv.x, qv.y, qv.z, qv.w};
            float kr[4] = {kv.x, kv.y, kv.z, kv.w};
#pragma unroll
            for (int i = 0; i < 4; i++)
#pragma unroll
                for (int j = 0; j < 4; j++)
                    s[i][j] = fmaf(qr[i], kr[j], s[i][j]);
        }

        // online softmax: reductions over the 16 tx lanes (xor 8..1 stays in-group)
#pragma unroll
        for (int i = 0; i < 4; i++) {
            float mx = fmaxf(fmaxf(s[i][0], s[i][1]), fmaxf(s[i][2], s[i][3]));
#pragma unroll
            for (int w = 8; w >= 1; w >>= 1)
                mx = fmaxf(mx, __shfl_xor_sync(0xffffffffu, mx, w));
            float mn = fmaxf(m[i], mx);
            float sf = expf(m[i] - mn);
            float sum = 0.f;
#pragma unroll
            for (int j = 0; j < 4; j++) {
                float p = expf(s[i][j] - mn);
                s[i][j] = p;
                sum += p;
            }
#pragma unroll
            for (int w = 8; w >= 1; w >>= 1)
                sum += __shfl_xor_sync(0xffffffffu, sum, w);
            l[i] = l[i] * sf + sum;
            m[i] = mn;
#pragma unroll
            for (int j = 0; j < 4; j++) o[i][j] *= sf;
        }

        // spill P transposed: ps[key][query] so the PV gemm reads float4 in query
#pragma unroll
        for (int j = 0; j < 4; j++) {
            float4 pv = make_float4(s[0][j], s[1][j], s[2][j], s[3][j]);
            *(float4*)&ps[(tx * 4 + j) * 68 + ty * 4] = pv;
        }
        __syncthreads();

        // O += P V
#pragma unroll
        for (int k = 0; k < 64; k++) {
            float4 pv = *(const float4*)&ps[k * 68 + ty * 4];
            float4 vv = *(const float4*)&vs[k * 64 + tx * 4];
            float pr[4] = {pv.x, pv.y, pv.z, pv.w};
            float vr[4] = {vv.x, vv.y, vv.z, vv.w};
#pragma unroll
            for (int i = 0; i < 4; i++)
#pragma unroll
                for (int j = 0; j < 4; j++)
                    o[i][j] = fmaf(pr[i], vr[j], o[i][j]);
        }
    }

    // epilogue: normalize and store
#pragma unroll
    for (int i = 0; i < 4; i++) {
        float inv = 1.f / l[i];
        float4 ov = make_float4(o[i][0] * inv, o[i][1] * inv,
                                o[i][2] * inv, o[i][3] * inv);
        *(float4*)&out[((size_t)b * T_ + q0 + ty * 4 + i) * H_ + tx * 4] = ov;
    }
}

// ---------------------------------------------------------------------------
extern "C" void kernel_launch(void* const* d_in, const int* in_sizes, int n_in,
                              void* d_out, int out_size) {
    const float* x  = (const float*)d_in[0];
    const float* Wq = (const float*)d_in[1];
    const float* Wk = (const float*)d_in[2];
    const float* Wv = (const float*)d_in[3];
    float* out = (float*)d_out;

    qkv_proj_kernel<<<(B_ * T_) / 64, 256>>>(x, Wq, Wk, Wv);

    cudaFuncSetAttribute(attn_kernel,
                         cudaFuncAttributeMaxDynamicSharedMemorySize, ATT_SMEM);
    attn_kernel<<<dim3(T_ / 64, B_), 256, ATT_SMEM>>>(out);
}

// round 4
// speedup vs baseline: 3.7955x; 3.7955x over previous
#include <cuda_runtime.h>
#include <math.h>
#include <stdint.h>

#define B_ 8
#define T_ 2048
#define C_ 512
#define H_ 64
#define SCALE 0.04419417382415922f   // 512^-0.5

__device__ float g_q[B_ * T_ * H_];
__device__ float g_k[B_ * T_ * H_];
__device__ float g_v[B_ * T_ * H_];

__device__ __forceinline__ unsigned f2tf(float x) {
    unsigned r; asm("cvt.rna.tf32.f32 %0, %1;" : "=r"(r) : "f"(x)); return r;
}
__device__ __forceinline__ void mma8(float* c, const unsigned* a, unsigned b0, unsigned b1) {
    asm volatile("mma.sync.aligned.m16n8k8.row.col.f32.tf32.tf32.f32 "
        "{%0,%1,%2,%3},{%4,%5,%6,%7},{%8,%9},{%0,%1,%2,%3};"
        : "+f"(c[0]), "+f"(c[1]), "+f"(c[2]), "+f"(c[3])
        : "r"(a[0]), "r"(a[1]), "r"(a[2]), "r"(a[3]), "r"(b0), "r"(b1));
}
__device__ __forceinline__ void cpa16(uint32_t s, const void* g) {
    asm volatile("cp.async.cg.shared.global [%0], [%1], 16;" :: "r"(s), "l"(g));
}
#define CP_COMMIT() asm volatile("cp.async.commit_group;")
#define CP_WAIT1()  asm volatile("cp.async.wait_group 1;")

// ===========================================================================
// Kernel 1: QKV projection, tf32 mma.  C[16384x192] = X[16384x512]*W[512x192]
// Block 256 thr (warps 4x2), tile M=128 N=96, k-chunks of 32, cp.async 2-buf.
// ===========================================================================
#define PX_STRIDE 36
#define PW_STRIDE 104
#define PXS(b) ((b) * 4608)
#define PWS(b) (9216 + (b) * 3328)
#define PROJ_SMEM (15872 * 4)

__global__ __launch_bounds__(256, 1) void qkv_proj(
    const float* __restrict__ x, const float* __restrict__ Wq,
    const float* __restrict__ Wk, const float* __restrict__ Wv) {
    extern __shared__ float sm[];
    const int tid = threadIdx.x;
    const int lane = tid & 31, warp = tid >> 5;
    const int wy = warp >> 1, wx = warp & 1;
    const int g = lane >> 2, q4 = lane & 3;
    const int m0 = blockIdx.x * 128;
    const int nb = blockIdx.y * 96;
    const float* Wmat[3] = {Wq, Wk, Wv};
    uint32_t smb = (uint32_t)__cvta_generic_to_shared(sm);

    float c[2][6][4];
#pragma unroll
    for (int i = 0; i < 2; i++)
#pragma unroll
        for (int j = 0; j < 6; j++)
#pragma unroll
            for (int r = 0; r < 4; r++) c[i][j][r] = 0.f;

    auto issue = [&](int kc, int buf) {
#pragma unroll
        for (int j = 0; j < 4; j++) {           // X: 1024 16B chunks
            int idx = tid + j * 256;
            int row = idx >> 3, ch = idx & 7;
            cpa16(smb + (uint32_t)(PXS(buf) + row * PX_STRIDE + ch * 4) * 4,
                  x + (size_t)(m0 + row) * C_ + kc * 32 + ch * 4);
        }
#pragma unroll
        for (int j = 0; j < 3; j++) {           // W: 768 16B chunks
            int idx = tid + j * 256;
            int row = idx / 24, ch = idx % 24;
            int ng = nb + ch * 4;
            const float* src = Wmat[ng >> 6] + (size_t)(kc * 32 + row) * H_ + (ng & 63);
            cpa16(smb + (uint32_t)(PWS(buf) + row * PW_STRIDE + ch * 4) * 4, src);
        }
    };
    issue(0, 0); CP_COMMIT();
    issue(1, 1); CP_COMMIT();

    for (int kc = 0; kc < 16; kc++) {
        CP_WAIT1(); __syncthreads();
        const float* xs = sm + PXS(kc & 1);
        const float* ws = sm + PWS(kc & 1);
#pragma unroll
        for (int s = 0; s < 4; s++) {
            unsigned a[2][4];
#pragma unroll
            for (int mf = 0; mf < 2; mf++) {
                const float* p = xs + (wy * 32 + mf * 16 + g) * PX_STRIDE + s * 8 + q4;
                a[mf][0] = f2tf(p[0]);
                a[mf][1] = f2tf(p[8 * PX_STRIDE]);
                a[mf][2] = f2tf(p[4]);
                a[mf][3] = f2tf(p[8 * PX_STRIDE + 4]);
            }
#pragma unroll
            for (int nf = 0; nf < 6; nf++) {
                const float* p = ws + (s * 8 + q4) * PW_STRIDE + wx * 48 + nf * 8 + g;
                unsigned b0 = f2tf(p[0]), b1 = f2tf(p[4 * PW_STRIDE]);
                mma8(c[0][nf], a[0], b0, b1);
                mma8(c[1][nf], a[1], b0, b1);
            }
        }
        __syncthreads();
        if (kc + 2 < 16) issue(kc + 2, kc & 1);
        CP_COMMIT();
    }

#pragma unroll
    for (int mf = 0; mf < 2; mf++) {
        int r0 = m0 + wy * 32 + mf * 16 + g;
#pragma unroll
        for (int nf = 0; nf < 6; nf++) {
            int ng = nb + wx * 48 + nf * 8 + 2 * q4;
            int mtx = ng >> 6, col = ng & 63;
            float* dst = (mtx == 0) ? g_q : (mtx == 1) ? g_k : g_v;
            float sc = (mtx == 0) ? SCALE : 1.f;
            *(float2*)&dst[(size_t)r0 * H_ + col] =
                make_float2(c[mf][nf][0] * sc, c[mf][nf][1] * sc);
            *(float2*)&dst[(size_t)(r0 + 8) * H_ + col] =
                make_float2(c[mf][nf][2] * sc, c[mf][nf][3] * sc);
        }
    }
}

// ===========================================================================
// Kernel 2: flash attention, tf32 mma.  Block = 128 queries, 8 warps (4x2).
// Warp (wy,wx): S rows wy*32..+32, keys wx*32..+32; O rows same, headdim wx*32.
// K/V double-buffered cp.async. P via 4-plane packed smem (conflict-free).
// ===========================================================================
#define AQ 0
#define AK(b) (8704 + (b) * 4352)
#define AV(b) (17408 + (b) * 4608)
#define APP 26624              /* 4 planes x 2056 */
#define ARMAX 34848
#define ARSUM 35104
#define ATT_SMEM (35360 * 4)

__global__ __launch_bounds__(256, 1) void attn_kernel(float* __restrict__ out) {
    extern __shared__ float sm[];
    const int tid = threadIdx.x;
    const int lane = tid & 31, warp = tid >> 5;
    const int wy = warp >> 1, wx = warp & 1;
    const int g = lane >> 2, q4 = lane & 3;
    const int b = blockIdx.y;
    const int q0 = blockIdx.x * 128;
    uint32_t smb = (uint32_t)__cvta_generic_to_shared(sm);

    const float* Qg = g_q + ((size_t)b * T_ + q0) * H_;
    const float* Kg = g_k + (size_t)b * T_ * H_;
    const float* Vg = g_v + (size_t)b * T_ * H_;

    // Q -> smem, tf32-rounded once (scale already folded in projection)
    for (int i = tid * 4; i < 128 * 64; i += 1024) {
        float4 v = *(const float4*)(Qg + i);
        int row = i >> 6, d = i & 63;
        float* p = sm + AQ + row * 68 + d;
        p[0] = __uint_as_float(f2tf(v.x));
        p[1] = __uint_as_float(f2tf(v.y));
        p[2] = __uint_as_float(f2tf(v.z));
        p[3] = __uint_as_float(f2tf(v.w));
    }

    // FIXED loader: full 64x64 tiles = 1024 chunks each for K and V.
    auto issue = [&](int t, int buf) {
#pragma unroll
        for (int j = 0; j < 4; j++) {
            int idx = tid + j * 256;
            int row = idx >> 4, ch = idx & 15;
            cpa16(smb + (uint32_t)(AK(buf) + row * 68 + ch * 4) * 4,
                  Kg + (size_t)(t * 64 + row) * H_ + ch * 4);
            cpa16(smb + (uint32_t)(AV(buf) + row * 72 + ch * 4) * 4,
                  Vg + (size_t)(t * 64 + row) * H_ + ch * 4);
        }
    };
    issue(0, 0); CP_COMMIT();
    issue(1, 1); CP_COMMIT();

    float mrow[4], lrow[4], o[2][4][4];
#pragma unroll
    for (int i = 0; i < 4; i++) { mrow[i] = -INFINITY; lrow[i] = 0.f; }
#pragma unroll
    for (int i = 0; i < 2; i++)
#pragma unroll
        for (int j = 0; j < 4; j++)
#pragma unroll
            for (int r = 0; r < 4; r++) o[i][j][r] = 0.f;

    for (int t = 0; t < 32; t++) {
        int bf = t & 1;
        CP_WAIT1(); __syncthreads();
        const float* K = sm + AK(bf);
        const float* V = sm + AV(bf);

        // ---- S = Q K^T ----
        float c[2][4][4];
#pragma unroll
        for (int i = 0; i < 2; i++)
#pragma unroll
            for (int j = 0; j < 4; j++)
#pragma unroll
                for (int r = 0; r < 4; r++) c[i][j][r] = 0.f;

#pragma unroll
        for (int s = 0; s < 8; s++) {
            unsigned a[2][4];
#pragma unroll
            for (int mf = 0; mf < 2; mf++) {
                const float* p = sm + AQ + (wy * 32 + mf * 16 + g) * 68 + s * 8 + q4;
                a[mf][0] = __float_as_uint(p[0]);
                a[mf][1] = __float_as_uint(p[8 * 68]);
                a[mf][2] = __float_as_uint(p[4]);
                a[mf][3] = __float_as_uint(p[8 * 68 + 4]);
            }
#pragma unroll
            for (int nf = 0; nf < 4; nf++) {
                const float* p = K + (wx * 32 + nf * 8 + g) * 68 + s * 8 + q4;
                unsigned b0 = f2tf(p[0]), b1 = f2tf(p[4]);
                mma8(c[0][nf], a[0], b0, b1);
                mma8(c[1][nf], a[1], b0, b1);
            }
        }

        // ---- online softmax (cross-warp pair via smem) ----
        float mloc[4], sco[4];
#pragma unroll
        for (int sl = 0; sl < 4; sl++) {
            int mf = sl >> 1, hi = sl & 1;
            float lm = -INFINITY;
#pragma unroll
            for (int nf = 0; nf < 4; nf++)
                lm = fmaxf(lm, fmaxf(c[mf][nf][hi * 2], c[mf][nf][hi * 2 + 1]));
            lm = fmaxf(lm, __shfl_xor_sync(0xffffffffu, lm, 1));
            lm = fmaxf(lm, __shfl_xor_sync(0xffffffffu, lm, 2));
            mloc[sl] = lm;
            int ridx = wy * 32 + mf * 16 + hi * 8 + g;
            if (q4 == 0) sm[ARMAX + wx * 128 + ridx] = lm;
        }
        __syncthreads();
#pragma unroll
        for (int sl = 0; sl < 4; sl++) {
            int ridx = wy * 32 + (sl >> 1) * 16 + (sl & 1) * 8 + g;
            float other = sm[ARMAX + (1 ^ wx) * 128 + ridx];
            float mn = fmaxf(mrow[sl], fmaxf(mloc[sl], other));
            sco[sl] = __expf(mrow[sl] - mn);
            mrow[sl] = mn;
        }
        float ls[4] = {0.f, 0.f, 0.f, 0.f};
#pragma unroll
        for (int mf = 0; mf < 2; mf++)
#pragma unroll
            for (int nf = 0; nf < 4; nf++) {
                int s_ = wx * 4 + nf;
                int base = (s_ * 8 + wy * 2 + mf) * 32;
#pragma unroll
                for (int r = 0; r < 4; r++) {
                    int sl = mf * 2 + (r >> 1);
                    float p = __expf(c[mf][nf][r] - mrow[sl]);
                    ls[sl] += p;
                    int cin = 2 * q4 + (r & 1);
                    int plane = (r >> 1) + 2 * (cin >> 2);
                    int La = g * 4 + (cin & 3);
                    sm[APP + plane * 2056 + base + La] = __uint_as_float(f2tf(p));
                }
            }
#pragma unroll
        for (int sl = 0; sl < 4; sl++) {
            ls[sl] += __shfl_xor_sync(0xffffffffu, ls[sl], 1);
            ls[sl] += __shfl_xor_sync(0xffffffffu, ls[sl], 2);
            int ridx = wy * 32 + (sl >> 1) * 16 + (sl & 1) * 8 + g;
            if (q4 == 0) sm[ARSUM + wx * 128 + ridx] = ls[sl];
        }
        __syncthreads();
#pragma unroll
        for (int sl = 0; sl < 4; sl++) {
            int ridx = wy * 32 + (sl >> 1) * 16 + (sl & 1) * 8 + g;
            float osum = sm[ARSUM + (1 ^ wx) * 128 + ridx];
            lrow[sl] = lrow[sl] * sco[sl] + ls[sl] + osum;
        }
#pragma unroll
        for (int mf = 0; mf < 2; mf++)
#pragma unroll
            for (int nf = 0; nf < 4; nf++)
#pragma unroll
                for (int r = 0; r < 4; r++)
                    o[mf][nf][r] *= sco[mf * 2 + (r >> 1)];

        // ---- O += P V ----
#pragma unroll
        for (int s = 0; s < 8; s++) {
            unsigned a[2][4];
#pragma unroll
            for (int mf = 0; mf < 2; mf++) {
                int idx = APP + (s * 8 + wy * 2 + mf) * 32 + lane;
#pragma unroll
                for (int r = 0; r < 4; r++)
                    a[mf][r] = __float_as_uint(sm[idx + r * 2056]);
            }
#pragma unroll
            for (int nf = 0; nf < 4; nf++) {
                int hc = wx * 32 + nf * 8 + g;
                unsigned b0 = f2tf(V[(s * 8 + q4) * 72 + hc]);
                unsigned b1 = f2tf(V[(s * 8 + q4 + 4) * 72 + hc]);
                mma8(o[0][nf], a[0], b0, b1);
                mma8(o[1][nf], a[1], b0, b1);
            }
        }
        __syncthreads();
        if (t + 2 < 32) issue(t + 2, bf);
        CP_COMMIT();
    }

    // ---- epilogue ----
#pragma unroll
    for (int mf = 0; mf < 2; mf++) {
        int r0 = q0 + wy * 32 + mf * 16 + g;
        float i0 = 1.f / lrow[mf * 2], i1 = 1.f / lrow[mf * 2 + 1];
#pragma unroll
        for (int nf = 0; nf < 4; nf++) {
            int col = wx * 32 + nf * 8 + 2 * q4;
            *(float2*)&out[((size_t)b * T_ + r0) * H_ + col] =
                make_float2(o[mf][nf][0] * i0, o[mf][nf][1] * i0);
            *(float2*)&out[((size_t)b * T_ + r0 + 8) * H_ + col] =
                make_float2(o[mf][nf][2] * i1, o[mf][nf][3] * i1);
        }
    }
}

// ===========================================================================
extern "C" void kernel_launch(void* const* d_in, const int* in_sizes, int n_in,
                              void* d_out, int out_size) {
    const float* x  = (const float*)d_in[0];
    const float* Wq = (const float*)d_in[1];
    const float* Wk = (const float*)d_in[2];
    const float* Wv = (const float*)d_in[3];
    float* out = (float*)d_out;

    cudaFuncSetAttribute(qkv_proj,
                         cudaFuncAttributeMaxDynamicSharedMemorySize, PROJ_SMEM);
    cudaFuncSetAttribute(attn_kernel,
                         cudaFuncAttributeMaxDynamicSharedMemorySize, ATT_SMEM);

    qkv_proj<<<dim3(128, 2), 256, PROJ_SMEM>>>(x, Wq, Wk, Wv);
    attn_kernel<<<dim3(16, 8), 256, ATT_SMEM>>>(out);
}

// round 8
// speedup vs baseline: 6.1188x; 1.6121x over previous
#include <cuda_runtime.h>
#include <cuda_fp16.h>
#include <math.h>
#include <stdint.h>

#define B_ 8
#define T_ 2048
#define C_ 512
#define H_ 64
#define SCALE 0.04419417382415922f   // 512^-0.5

__device__ __half g_q[B_ * T_ * H_];
__device__ __half g_k[B_ * T_ * H_];
__device__ __half g_v[B_ * T_ * H_];

__device__ __forceinline__ unsigned f2tf(float x) {
    unsigned r; asm("cvt.rna.tf32.f32 %0, %1;" : "=r"(r) : "f"(x)); return r;
}
__device__ __forceinline__ unsigned h2u(__half2 h) {
    return *reinterpret_cast<unsigned*>(&h);
}
__device__ __forceinline__ void mma8(float* c, const unsigned* a, unsigned b0, unsigned b1) {
    asm volatile("mma.sync.aligned.m16n8k8.row.col.f32.tf32.tf32.f32 "
        "{%0,%1,%2,%3},{%4,%5,%6,%7},{%8,%9},{%0,%1,%2,%3};"
        : "+f"(c[0]), "+f"(c[1]), "+f"(c[2]), "+f"(c[3])
        : "r"(a[0]), "r"(a[1]), "r"(a[2]), "r"(a[3]), "r"(b0), "r"(b1));
}
__device__ __forceinline__ void mmah(float* c, const unsigned* a, unsigned b0, unsigned b1) {
    asm volatile("mma.sync.aligned.m16n8k16.row.col.f32.f16.f16.f32 "
        "{%0,%1,%2,%3},{%4,%5,%6,%7},{%8,%9},{%0,%1,%2,%3};"
        : "+f"(c[0]), "+f"(c[1]), "+f"(c[2]), "+f"(c[3])
        : "r"(a[0]), "r"(a[1]), "r"(a[2]), "r"(a[3]), "r"(b0), "r"(b1));
}
__device__ __forceinline__ void ldsm4(unsigned& r0, unsigned& r1, unsigned& r2,
                                      unsigned& r3, uint32_t a) {
    asm volatile("ldmatrix.sync.aligned.m8n8.x4.shared.b16 {%0,%1,%2,%3}, [%4];"
        : "=r"(r0), "=r"(r1), "=r"(r2), "=r"(r3) : "r"(a));
}
__device__ __forceinline__ void ldsm4t(unsigned& r0, unsigned& r1, unsigned& r2,
                                       unsigned& r3, uint32_t a) {
    asm volatile("ldmatrix.sync.aligned.m8n8.x4.trans.shared.b16 {%0,%1,%2,%3}, [%4];"
        : "=r"(r0), "=r"(r1), "=r"(r2), "=r"(r3) : "r"(a));
}
__device__ __forceinline__ void cpa16(uint32_t s, const void* g) {
    asm volatile("cp.async.cg.shared.global [%0], [%1], 16;" :: "r"(s), "l"(g));
}
#define CP_COMMIT() asm volatile("cp.async.commit_group;")
#define CP_WAIT1()  asm volatile("cp.async.wait_group 1;")
#define CP_WAIT2()  asm volatile("cp.async.wait_group 2;")

// ===========================================================================
// Kernel 1: QKV projection (tf32 mma), epilogue stores fp16.
// ===========================================================================
#define PX_STRIDE 36
#define PW_STRIDE 104
#define PXS(b) ((b) * 4608)
#define PWS(b) (9216 + (b) * 3328)
#define PROJ_SMEM (15872 * 4)

__global__ __launch_bounds__(256, 1) void qkv_proj(
    const float* __restrict__ x, const float* __restrict__ Wq,
    const float* __restrict__ Wk, const float* __restrict__ Wv) {
    extern __shared__ float sm[];
    const int tid = threadIdx.x;
    const int lane = tid & 31, warp = tid >> 5;
    const int wy = warp >> 1, wx = warp & 1;
    const int g = lane >> 2, q4 = lane & 3;
    const int m0 = blockIdx.x * 128;
    const int nb = blockIdx.y * 96;
    const float* Wmat[3] = {Wq, Wk, Wv};
    uint32_t smb = (uint32_t)__cvta_generic_to_shared(sm);

    float c[2][6][4];
#pragma unroll
    for (int i = 0; i < 2; i++)
#pragma unroll
        for (int j = 0; j < 6; j++)
#pragma unroll
            for (int r = 0; r < 4; r++) c[i][j][r] = 0.f;

    auto issue = [&](int kc, int buf) {
#pragma unroll
        for (int j = 0; j < 4; j++) {
            int idx = tid + j * 256;
            int row = idx >> 3, ch = idx & 7;
            cpa16(smb + (uint32_t)(PXS(buf) + row * PX_STRIDE + ch * 4) * 4,
                  x + (size_t)(m0 + row) * C_ + kc * 32 + ch * 4);
        }
#pragma unroll
        for (int j = 0; j < 3; j++) {
            int idx = tid + j * 256;
            int row = idx / 24, ch = idx % 24;
            int ng = nb + ch * 4;
            const float* src = Wmat[ng >> 6] + (size_t)(kc * 32 + row) * H_ + (ng & 63);
            cpa16(smb + (uint32_t)(PWS(buf) + row * PW_STRIDE + ch * 4) * 4, src);
        }
    };
    issue(0, 0); CP_COMMIT();
    issue(1, 1); CP_COMMIT();

    for (int kc = 0; kc < 16; kc++) {
        CP_WAIT1(); __syncthreads();
        const float* xs = sm + PXS(kc & 1);
        const float* ws = sm + PWS(kc & 1);
#pragma unroll
        for (int s = 0; s < 4; s++) {
            unsigned a[2][4];
#pragma unroll
            for (int mf = 0; mf < 2; mf++) {
                const float* p = xs + (wy * 32 + mf * 16 + g) * PX_STRIDE + s * 8 + q4;
                a[mf][0] = f2tf(p[0]);
                a[mf][1] = f2tf(p[8 * PX_STRIDE]);
                a[mf][2] = f2tf(p[4]);
                a[mf][3] = f2tf(p[8 * PX_STRIDE + 4]);
            }
#pragma unroll
            for (int nf = 0; nf < 6; nf++) {
                const float* p = ws + (s * 8 + q4) * PW_STRIDE + wx * 48 + nf * 8 + g;
                unsigned b0 = f2tf(p[0]), b1 = f2tf(p[4 * PW_STRIDE]);
                mma8(c[0][nf], a[0], b0, b1);
                mma8(c[1][nf], a[1], b0, b1);
            }
        }
        __syncthreads();
        if (kc + 2 < 16) issue(kc + 2, kc & 1);
        CP_COMMIT();
    }

#pragma unroll
    for (int mf = 0; mf < 2; mf++) {
        int r0 = m0 + wy * 32 + mf * 16 + g;
#pragma unroll
        for (int nf = 0; nf < 6; nf++) {
            int ng = nb + wx * 48 + nf * 8 + 2 * q4;
            int mtx = ng >> 6, col = ng & 63;
            __half* dst = (mtx == 0) ? g_q : (mtx == 1) ? g_k : g_v;
            float sc = (mtx == 0) ? SCALE : 1.f;
            *(__half2*)&dst[(size_t)r0 * H_ + col] =
                __floats2half2_rn(c[mf][nf][0] * sc, c[mf][nf][1] * sc);
            *(__half2*)&dst[(size_t)(r0 + 8) * H_ + col] =
                __floats2half2_rn(c[mf][nf][2] * sc, c[mf][nf][3] * sc);
        }
    }
}

// ===========================================================================
// Kernel 2: flash attention, fp16 mma (m16n8k16), warp-owns-rows design.
// Block = 128 queries, 8 warps; warp w owns rows w*16..w*16+15 and ALL keys.
// Softmax fully warp-local; P stays in registers (C->A fragment match).
// K/V in smem as half, stride 72 halves (144B), 3-stage cp.async pipeline.
// ===========================================================================
#define KV_STRIDE 72                       /* halves, 144 B rows */
#define KB(s) ((s) * 4608)                 /* half offsets */
#define VB(s) (13824 + (s) * 4608)
#define ATT_SMEM (27648 * 2)               /* 55296 bytes */

__global__ __launch_bounds__(256, 1) void attn_kernel(float* __restrict__ out) {
    extern __shared__ __half smh[];
    const int tid = threadIdx.x;
    const int lane = tid & 31, warp = tid >> 5;
    const int g = lane >> 2, q4 = lane & 3;
    const int b = blockIdx.y;
    const int q0 = blockIdx.x * 128;
    uint32_t smb = (uint32_t)__cvta_generic_to_shared(smh);

    const __half* Qg = g_q + ((size_t)b * T_ + q0) * H_;
    const __half* Kg = g_k + (size_t)b * T_ * H_;
    const __half* Vg = g_v + (size_t)b * T_ * H_;

    // Q fragments -> registers (scale already folded; fp16 storage = rounding)
    unsigned qa[4][4];
#pragma unroll
    for (int s = 0; s < 4; s++) {
        const __half* p = Qg + (warp * 16 + g) * H_ + s * 16 + 2 * q4;
        qa[s][0] = *(const unsigned*)(p);
        qa[s][1] = *(const unsigned*)(p + 8 * H_);
        qa[s][2] = *(const unsigned*)(p + 8);
        qa[s][3] = *(const unsigned*)(p + 8 * H_ + 8);
    }

    // tile loader: K and V 64x64 half tiles (512 16B chunks each)
    auto issue = [&](int t, int buf) {
#pragma unroll
        for (int j = 0; j < 2; j++) {
            int idx = tid + j * 256;
            int row = idx >> 3, ch = idx & 7;
            uint32_t off = (uint32_t)(row * KV_STRIDE + ch * 8) * 2;
            const __half* src = Kg + (size_t)(t * 64 + row) * H_ + ch * 8;
            cpa16(smb + (uint32_t)KB(buf) * 2 + off, src);
            const __half* srcv = Vg + (size_t)(t * 64 + row) * H_ + ch * 8;
            cpa16(smb + (uint32_t)VB(buf) * 2 + off, srcv);
        }
    };
    issue(0, 0); CP_COMMIT();
    issue(1, 1); CP_COMMIT();
    issue(2, 2); CP_COMMIT();

    // ldmatrix lane address components
    const int m_hi = lane >> 4;            // m>>1
    const int m_lo = (lane >> 3) & 1;      // m&1
    const int r8 = lane & 7;
    const uint32_t k_lane = (uint32_t)((m_hi * 8 + r8) * KV_STRIDE + m_lo * 8) * 2;
    const uint32_t v_lane = (uint32_t)((m_lo * 8 + r8) * KV_STRIDE + m_hi * 8) * 2;

    float mrow[2], lrow[2], o[8][4];
    mrow[0] = mrow[1] = -INFINITY;
    lrow[0] = lrow[1] = 0.f;
#pragma unroll
    for (int j = 0; j < 8; j++)
#pragma unroll
        for (int r = 0; r < 4; r++) o[j][r] = 0.f;

    for (int t = 0; t < 32; t++) {
        int bf = t % 3;
        CP_WAIT2(); __syncthreads();
        const uint32_t kbase = smb + (uint32_t)KB(bf) * 2 + k_lane;
        const uint32_t vbase = smb + (uint32_t)VB(bf) * 2 + v_lane;

        // ---- S = Q K^T : c[nf] covers keys nf*8..nf*8+7 ----
        float c[8][4];
#pragma unroll
        for (int j = 0; j < 8; j++)
#pragma unroll
            for (int r = 0; r < 4; r++) c[j][r] = 0.f;

#pragma unroll
        for (int s = 0; s < 4; s++) {
#pragma unroll
            for (int nfp = 0; nfp < 8; nfp += 2) {
                unsigned b0, b1, b2, b3;
                ldsm4(b0, b1, b2, b3,
                      kbase + (uint32_t)(nfp * 8 * KV_STRIDE + s * 16) * 2);
                mmah(c[nfp], qa[s], b0, b1);
                mmah(c[nfp + 1], qa[s], b2, b3);
            }
        }

        // ---- warp-local online softmax (rows g and g+8) ----
        unsigned pa[4][4];
#pragma unroll
        for (int h = 0; h < 2; h++) {
            float mx = -INFINITY;
#pragma unroll
            for (int nf = 0; nf < 8; nf++)
                mx = fmaxf(mx, fmaxf(c[nf][h * 2], c[nf][h * 2 + 1]));
            mx = fmaxf(mx, __shfl_xor_sync(0xffffffffu, mx, 1));
            mx = fmaxf(mx, __shfl_xor_sync(0xffffffffu, mx, 2));
            float mn = fmaxf(mrow[h], mx);
            float sco = __expf(mrow[h] - mn);
            mrow[h] = mn;
            float sum = 0.f;
#pragma unroll
            for (int nf = 0; nf < 8; nf++) {
                float p0 = __expf(c[nf][h * 2] - mn);
                float p1 = __expf(c[nf][h * 2 + 1] - mn);
                c[nf][h * 2] = p0; c[nf][h * 2 + 1] = p1;
                sum += p0 + p1;
            }
            sum += __shfl_xor_sync(0xffffffffu, sum, 1);
            sum += __shfl_xor_sync(0xffffffffu, sum, 2);
            lrow[h] = lrow[h] * sco + sum;
#pragma unroll
            for (int nf = 0; nf < 8; nf++)
#pragma unroll
                for (int r = 0; r < 2; r++) o[nf][h * 2 + r] *= sco;
        }
        // pack P into fp16 A-fragments (C->A layout match)
#pragma unroll
        for (int s = 0; s < 4; s++) {
            pa[s][0] = h2u(__floats2half2_rn(c[2 * s][0], c[2 * s][1]));
            pa[s][1] = h2u(__floats2half2_rn(c[2 * s][2], c[2 * s][3]));
            pa[s][2] = h2u(__floats2half2_rn(c[2 * s + 1][0], c[2 * s + 1][1]));
            pa[s][3] = h2u(__floats2half2_rn(c[2 * s + 1][2], c[2 * s + 1][3]));
        }

        // ---- O += P V : o[nf] covers headdim nf*8..+7 ----
#pragma unroll
        for (int s = 0; s < 4; s++) {
#pragma unroll
            for (int nfp = 0; nfp < 8; nfp += 2) {
                unsigned b0, b1, b2, b3;
                ldsm4t(b0, b1, b2, b3,
                       vbase + (uint32_t)(s * 16 * KV_STRIDE + nfp * 8) * 2);
                mmah(o[nfp], pa[s], b0, b1);
                mmah(o[nfp + 1], pa[s], b2, b3);
            }
        }

        __syncthreads();
        if (t + 3 < 32) issue(t + 3, bf);
        CP_COMMIT();
    }

    // ---- epilogue ----
    float i0 = 1.f / lrow[0], i1 = 1.f / lrow[1];
    size_t r0 = (size_t)b * T_ + q0 + warp * 16 + g;
#pragma unroll
    for (int nf = 0; nf < 8; nf++) {
        int col = nf * 8 + 2 * q4;
        *(float2*)&out[r0 * H_ + col] = make_float2(o[nf][0] * i0, o[nf][1] * i0);
        *(float2*)&out[(r0 + 8) * H_ + col] = make_float2(o[nf][2] * i1, o[nf][3] * i1);
    }
}

// ===========================================================================
extern "C" void kernel_launch(void* const* d_in, const int* in_sizes, int n_in,
                              void* d_out, int out_size) {
    const float* x  = (const float*)d_in[0];
    const float* Wq = (const float*)d_in[1];
    const float* Wk = (const float*)d_in[2];
    const float* Wv = (const float*)d_in[3];
    float* out = (float*)d_out;

    cudaFuncSetAttribute(qkv_proj,
                         cudaFuncAttributeMaxDynamicSharedMemorySize, PROJ_SMEM);
    cudaFuncSetAttribute(attn_kernel,
                         cudaFuncAttributeMaxDynamicSharedMemorySize, ATT_SMEM);

    qkv_proj<<<dim3(128, 2), 256, PROJ_SMEM>>>(x, Wq, Wk, Wv);
    attn_kernel<<<dim3(16, 8), 256, ATT_SMEM>>>(out);
}

// round 10
// speedup vs baseline: 6.3445x; 1.0369x over previous
#include <cuda_runtime.h>
#include <cuda_fp16.h>
#include <math.h>
#include <stdint.h>

#define B_ 8
#define T_ 2048
#define C_ 512
#define H_ 64
#define SCALE 0.04419417382415922f   // 512^-0.5

__device__ __half g_q[B_ * T_ * H_];
__device__ __half g_k[B_ * T_ * H_];
__device__ __half g_v[B_ * T_ * H_];

__device__ __forceinline__ unsigned f2tf(float x) {
    unsigned r; asm("cvt.rna.tf32.f32 %0, %1;" : "=r"(r) : "f"(x)); return r;
}
__device__ __forceinline__ unsigned h2u(__half2 h) {
    return *reinterpret_cast<unsigned*>(&h);
}
__device__ __forceinline__ void mma8(float* c, const unsigned* a, unsigned b0, unsigned b1) {
    asm volatile("mma.sync.aligned.m16n8k8.row.col.f32.tf32.tf32.f32 "
        "{%0,%1,%2,%3},{%4,%5,%6,%7},{%8,%9},{%0,%1,%2,%3};"
        : "+f"(c[0]), "+f"(c[1]), "+f"(c[2]), "+f"(c[3])
        : "r"(a[0]), "r"(a[1]), "r"(a[2]), "r"(a[3]), "r"(b0), "r"(b1));
}
__device__ __forceinline__ void mmah(float* c, const unsigned* a, unsigned b0, unsigned b1) {
    asm volatile("mma.sync.aligned.m16n8k16.row.col.f32.f16.f16.f32 "
        "{%0,%1,%2,%3},{%4,%5,%6,%7},{%8,%9},{%0,%1,%2,%3};"
        : "+f"(c[0]), "+f"(c[1]), "+f"(c[2]), "+f"(c[3])
        : "r"(a[0]), "r"(a[1]), "r"(a[2]), "r"(a[3]), "r"(b0), "r"(b1));
}
__device__ __forceinline__ void ldsm4(unsigned& r0, unsigned& r1, unsigned& r2,
                                      unsigned& r3, uint32_t a) {
    asm volatile("ldmatrix.sync.aligned.m8n8.x4.shared.b16 {%0,%1,%2,%3}, [%4];"
        : "=r"(r0), "=r"(r1), "=r"(r2), "=r"(r3) : "r"(a));
}
__device__ __forceinline__ void ldsm4t(unsigned& r0, unsigned& r1, unsigned& r2,
                                       unsigned& r3, uint32_t a) {
    asm volatile("ldmatrix.sync.aligned.m8n8.x4.trans.shared.b16 {%0,%1,%2,%3}, [%4];"
        : "=r"(r0), "=r"(r1), "=r"(r2), "=r"(r3) : "r"(a));
}
__device__ __forceinline__ void cpa16(uint32_t s, const void* g) {
    asm volatile("cp.async.cg.shared.global [%0], [%1], 16;" :: "r"(s), "l"(g));
}
#define CP_COMMIT() asm volatile("cp.async.commit_group;")
#define CP_WAIT1()  asm volatile("cp.async.wait_group 1;")
#define CP_WAIT2()  asm volatile("cp.async.wait_group 2;")

// ===========================================================================
// Kernel 1: QKV projection (tf32 mma), epilogue stores fp16.  (unchanged)
// ===========================================================================
#define PX_STRIDE 36
#define PW_STRIDE 104
#define PXS(b) ((b) * 4608)
#define PWS(b) (9216 + (b) * 3328)
#define PROJ_SMEM (15872 * 4)

__global__ __launch_bounds__(256, 1) void qkv_proj(
    const float* __restrict__ x, const float* __restrict__ Wq,
    const float* __restrict__ Wk, const float* __restrict__ Wv) {
    extern __shared__ float sm[];
    const int tid = threadIdx.x;
    const int lane = tid & 31, warp = tid >> 5;
    const int wy = warp >> 1, wx = warp & 1;
    const int g = lane >> 2, q4 = lane & 3;
    const int m0 = blockIdx.x * 128;
    const int nb = blockIdx.y * 96;
    const float* Wmat[3] = {Wq, Wk, Wv};
    uint32_t smb = (uint32_t)__cvta_generic_to_shared(sm);

    float c[2][6][4];
#pragma unroll
    for (int i = 0; i < 2; i++)
#pragma unroll
        for (int j = 0; j < 6; j++)
#pragma unroll
            for (int r = 0; r < 4; r++) c[i][j][r] = 0.f;

    auto issue = [&](int kc, int buf) {
#pragma unroll
        for (int j = 0; j < 4; j++) {
            int idx = tid + j * 256;
            int row = idx >> 3, ch = idx & 7;
            cpa16(smb + (uint32_t)(PXS(buf) + row * PX_STRIDE + ch * 4) * 4,
                  x + (size_t)(m0 + row) * C_ + kc * 32 + ch * 4);
        }
#pragma unroll
        for (int j = 0; j < 3; j++) {
            int idx = tid + j * 256;
            int row = idx / 24, ch = idx % 24;
            int ng = nb + ch * 4;
            const float* src = Wmat[ng >> 6] + (size_t)(kc * 32 + row) * H_ + (ng & 63);
            cpa16(smb + (uint32_t)(PWS(buf) + row * PW_STRIDE + ch * 4) * 4, src);
        }
    };
    issue(0, 0); CP_COMMIT();
    issue(1, 1); CP_COMMIT();

    for (int kc = 0; kc < 16; kc++) {
        CP_WAIT1(); __syncthreads();
        const float* xs = sm + PXS(kc & 1);
        const float* ws = sm + PWS(kc & 1);
#pragma unroll
        for (int s = 0; s < 4; s++) {
            unsigned a[2][4];
#pragma unroll
            for (int mf = 0; mf < 2; mf++) {
                const float* p = xs + (wy * 32 + mf * 16 + g) * PX_STRIDE + s * 8 + q4;
                a[mf][0] = f2tf(p[0]);
                a[mf][1] = f2tf(p[8 * PX_STRIDE]);
                a[mf][2] = f2tf(p[4]);
                a[mf][3] = f2tf(p[8 * PX_STRIDE + 4]);
            }
#pragma unroll
            for (int nf = 0; nf < 6; nf++) {
                const float* p = ws + (s * 8 + q4) * PW_STRIDE + wx * 48 + nf * 8 + g;
                unsigned b0 = f2tf(p[0]), b1 = f2tf(p[4 * PW_STRIDE]);
                mma8(c[0][nf], a[0], b0, b1);
                mma8(c[1][nf], a[1], b0, b1);
            }
        }
        __syncthreads();
        if (kc + 2 < 16) issue(kc + 2, kc & 1);
        CP_COMMIT();
    }

#pragma unroll
    for (int mf = 0; mf < 2; mf++) {
        int r0 = m0 + wy * 32 + mf * 16 + g;
#pragma unroll
        for (int nf = 0; nf < 6; nf++) {
            int ng = nb + wx * 48 + nf * 8 + 2 * q4;
            int mtx = ng >> 6, col = ng & 63;
            __half* dst = (mtx == 0) ? g_q : (mtx == 1) ? g_k : g_v;
            float sc = (mtx == 0) ? SCALE : 1.f;
            *(__half2*)&dst[(size_t)r0 * H_ + col] =
                __floats2half2_rn(c[mf][nf][0] * sc, c[mf][nf][1] * sc);
            *(__half2*)&dst[(size_t)(r0 + 8) * H_ + col] =
                __floats2half2_rn(c[mf][nf][2] * sc, c[mf][nf][3] * sc);
        }
    }
}

// ===========================================================================
// Kernel 2: flash attention, fp16 mma. 64-query blocks, 128 threads (4 warps),
// 4 blocks/SM (16 warps/SM) for latency hiding.  Warp owns 16 rows, all keys.
// Softmax warp-local; P in registers; l-sum reduction deferred to epilogue.
// ===========================================================================
#define KV_STRIDE 72                       /* halves, 144 B rows */
#define KB(s) ((s) * 4608)                 /* half offsets */
#define VB(s) (13824 + (s) * 4608)
#define ATT_SMEM (27648 * 2)               /* 55296 bytes */

__global__ __launch_bounds__(128, 4) void attn_kernel(float* __restrict__ out) {
    extern __shared__ __half smh[];
    const int tid = threadIdx.x;
    const int lane = tid & 31, warp = tid >> 5;
    const int g = lane >> 2, q4 = lane & 3;
    const int b = blockIdx.y;
    const int q0 = blockIdx.x * 64;
    uint32_t smb = (uint32_t)__cvta_generic_to_shared(smh);

    const __half* Qg = g_q + ((size_t)b * T_ + q0) * H_;
    const __half* Kg = g_k + (size_t)b * T_ * H_;
    const __half* Vg = g_v + (size_t)b * T_ * H_;

    // Q fragments -> registers
    unsigned qa[4][4];
#pragma unroll
    for (int s = 0; s < 4; s++) {
        const __half* p = Qg + (warp * 16 + g) * H_ + s * 16 + 2 * q4;
        qa[s][0] = *(const unsigned*)(p);
        qa[s][1] = *(const unsigned*)(p + 8 * H_);
        qa[s][2] = *(const unsigned*)(p + 8);
        qa[s][3] = *(const unsigned*)(p + 8 * H_ + 8);
    }

    // tile loader: K and V 64x64 half tiles, 512 16B chunks each, 128 threads
    auto issue = [&](int t, int buf) {
#pragma unroll
        for (int j = 0; j < 4; j++) {
            int idx = tid + j * 128;
            int row = idx >> 3, ch = idx & 7;
            uint32_t off = (uint32_t)(row * KV_STRIDE + ch * 8) * 2;
            cpa16(smb + (uint32_t)KB(buf) * 2 + off,
                  Kg + (size_t)(t * 64 + row) * H_ + ch * 8);
            cpa16(smb + (uint32_t)VB(buf) * 2 + off,
                  Vg + (size_t)(t * 64 + row) * H_ + ch * 8);
        }
    };
    issue(0, 0); CP_COMMIT();
    issue(1, 1); CP_COMMIT();
    issue(2, 2); CP_COMMIT();

    // ldmatrix lane address components
    const int m_hi = lane >> 4;
    const int m_lo = (lane >> 3) & 1;
    const int r8 = lane & 7;
    const uint32_t k_lane = (uint32_t)((m_hi * 8 + r8) * KV_STRIDE + m_lo * 8) * 2;
    const uint32_t v_lane = (uint32_t)((m_lo * 8 + r8) * KV_STRIDE + m_hi * 8) * 2;

    float mrow[2], lrow[2], o[8][4];
    mrow[0] = mrow[1] = -INFINITY;
    lrow[0] = lrow[1] = 0.f;                // per-lane partial sums (deferred)
#pragma unroll
    for (int j = 0; j < 8; j++)
#pragma unroll
        for (int r = 0; r < 4; r++) o[j][r] = 0.f;

    for (int t = 0; t < 32; t++) {
        int bf = t % 3;
        CP_WAIT2(); __syncthreads();
        const uint32_t kbase = smb + (uint32_t)KB(bf) * 2 + k_lane;
        const uint32_t vbase = smb + (uint32_t)VB(bf) * 2 + v_lane;

        // ---- S = Q K^T ----
        float c[8][4];
#pragma unroll
        for (int j = 0; j < 8; j++)
#pragma unroll
            for (int r = 0; r < 4; r++) c[j][r] = 0.f;

#pragma unroll
        for (int s = 0; s < 4; s++) {
#pragma unroll
            for (int nfp = 0; nfp < 8; nfp += 2) {
                unsigned b0, b1, b2, b3;
                ldsm4(b0, b1, b2, b3,
                      kbase + (uint32_t)(nfp * 8 * KV_STRIDE + s * 16) * 2);
                mmah(c[nfp], qa[s], b0, b1);
                mmah(c[nfp + 1], qa[s], b2, b3);
            }
        }

        // ---- warp-local online softmax (rows g and g+8) ----
        unsigned pa[4][4];
#pragma unroll
        for (int h = 0; h < 2; h++) {
            float mx = -INFINITY;
#pragma unroll
            for (int nf = 0; nf < 8; nf++)
                mx = fmaxf(mx, fmaxf(c[nf][h * 2], c[nf][h * 2 + 1]));
            mx = fmaxf(mx, __shfl_xor_sync(0xffffffffu, mx, 1));
            mx = fmaxf(mx, __shfl_xor_sync(0xffffffffu, mx, 2));
            float mn = fmaxf(mrow[h], mx);
            float sco = __expf(mrow[h] - mn);
            mrow[h] = mn;
            float sum = 0.f;
#pragma unroll
            for (int nf = 0; nf < 8; nf++) {
                float p0 = __expf(c[nf][h * 2] - mn);
                float p1 = __expf(c[nf][h * 2 + 1] - mn);
                c[nf][h * 2] = p0; c[nf][h * 2 + 1] = p1;
                sum += p0 + p1;
            }
            // deferred: keep per-lane partial, reduce across lanes after loop
            lrow[h] = lrow[h] * sco + sum;
#pragma unroll
            for (int nf = 0; nf < 8; nf++)
#pragma unroll
                for (int r = 0; r < 2; r++) o[nf][h * 2 + r] *= sco;
        }
        // pack P into fp16 A-fragments (C->A layout match)
#pragma unroll
        for (int s = 0; s < 4; s++) {
            pa[s][0] = h2u(__floats2half2_rn(c[2 * s][0], c[2 * s][1]));
            pa[s][1] = h2u(__floats2half2_rn(c[2 * s][2], c[2 * s][3]));
            pa[s][2] = h2u(__floats2half2_rn(c[2 * s + 1][0], c[2 * s + 1][1]));
            pa[s][3] = h2u(__floats2half2_rn(c[2 * s + 1][2], c[2 * s + 1][3]));
        }

        // ---- O += P V ----
#pragma unroll
        for (int s = 0; s < 4; s++) {
#pragma unroll
            for (int nfp = 0; nfp < 8; nfp += 2) {
                unsigned b0, b1, b2, b3;
                ldsm4t(b0, b1, b2, b3,
                       vbase + (uint32_t)(s * 16 * KV_STRIDE + nfp * 8) * 2);
                mmah(o[nfp], pa[s], b0, b1);
                mmah(o[nfp + 1], pa[s], b2, b3);
            }
        }

        __syncthreads();
        if (t + 3 < 32) issue(t + 3, bf);
        CP_COMMIT();
    }

    // ---- epilogue: finish deferred l reduction, normalize, store ----
#pragma unroll
    for (int h = 0; h < 2; h++) {
        lrow[h] += __shfl_xor_sync(0xffffffffu, lrow[h], 1);
        lrow[h] += __shfl_xor_sync(0xffffffffu, lrow[h], 2);
    }
    float i0 = 1.f / lrow[0], i1 = 1.f / lrow[1];
    size_t r0 = (size_t)b * T_ + q0 + warp * 16 + g;
#pragma unroll
    for (int nf = 0; nf < 8; nf++) {
        int col = nf * 8 + 2 * q4;
        *(float2*)&out[r0 * H_ + col] = make_float2(o[nf][0] * i0, o[nf][1] * i0);
        *(float2*)&out[(r0 + 8) * H_ + col] = make_float2(o[nf][2] * i1, o[nf][3] * i1);
    }
}

// ===========================================================================
extern "C" void kernel_launch(void* const* d_in, const int* in_sizes, int n_in,
                              void* d_out, int out_size) {
    const float* x  = (const float*)d_in[0];
    const float* Wq = (const float*)d_in[1];
    const float* Wk = (const float*)d_in[2];
    const float* Wv = (const float*)d_in[3];
    float* out = (float*)d_out;

    cudaFuncSetAttribute(qkv_proj,
                         cudaFuncAttributeMaxDynamicSharedMemorySize, PROJ_SMEM);
    cudaFuncSetAttribute(attn_kernel,
                         cudaFuncAttributeMaxDynamicSharedMemorySize, ATT_SMEM);

    qkv_proj<<<dim3(128, 2), 256, PROJ_SMEM>>>(x, Wq, Wk, Wv);
    attn_kernel<<<dim3(32, 8), 128, ATT_SMEM>>>(out);
}